// round 8
// baseline (speedup 1.0000x reference)
#include <cuda_runtime.h>
#include <math_constants.h>

#define HFEAT 200
#define WFEAT 320
#define HWFEAT (HFEAT * WFEAT)      // 64000 pixels
#define HW4 (HWFEAT / 4)            // 16000 pixel-quads
#define CFEAT 256
#define NROI 128
#define MSZ 14
#define NBIN (MSZ * MSZ)            // 196
#define NCB 16                      // fine channel blocks (16 channels each)
#define CPB 16
#define NCAND (NROI * 4)            // 512 candidates per bin
#define NSEED 8                     // seed rois per bin
#define COLMAX_BLOCKS (HW4 / 16)    // 1000
#define PREP_BLOCKS (COLMAX_BLOCKS + NBIN)

// Scratch (static device arrays — no allocation)
__device__ __align__(16) float g_Mb[HWFEAT * NCB];   // per-pixel 16-ch block maxes (4 MB)
__device__ __align__(16) float g_Tm[HWFEAT];         // per-pixel total max (256 KB)
__device__ __align__(16) float g_best[NBIN];         // per-bin running exact lower bound

// ---------------------------------------------------------------------------
__device__ __forceinline__ void atomicMaxFloat(float* addr, float val) {
    if (val >= 0.0f) {
        atomicMax((int*)addr, __float_as_int(val));
    } else {
        atomicMin((unsigned int*)addr, __float_as_uint(val));
    }
}

// ---------------------------------------------------------------------------
// Geometry: replicate the reference bilinear setup exactly
// (corner indices clamped FIRST, weights computed from clamped corners).
// ---------------------------------------------------------------------------
struct Geom {
    int o11, o12, o21, o22;
    float wy_lo, wy_hi, wx_lo, wx_hi;
    bool wok;   // weights are a convex combination (clamp did not trigger)
};

__device__ __forceinline__ Geom make_geom(const float* __restrict__ rois,
                                          int r, int s, int m, int n) {
    float r0 = __ldg(&rois[r * 4 + 0]);
    float r1 = __ldg(&rois[r * 4 + 1]);
    float r2 = __ldg(&rois[r * 4 + 2]);
    float r3 = __ldg(&rois[r * 4 + 3]);
    float sh = (r2 - r0) / 14.0f;
    float sw = (r3 - r1) / 14.0f;
    float fy = (s >> 1) ? (2.0f / 3.0f) : (1.0f / 3.0f);
    float fx = (s & 1)  ? (2.0f / 3.0f) : (1.0f / 3.0f);
    float y = (r0 + sh * (float)m) + sh * fy;
    float x = (r1 + sw * (float)n) + sw * fx;

    int yf = (int)floorf(y);
    int xf = (int)floorf(x);
    int y1c = min(max(yf, 0), HFEAT - 1);
    int y2c = min(max(yf + 1, 0), HFEAT - 1);
    int x1c = min(max(xf, 0), WFEAT - 1);
    int x2c = min(max(xf + 1, 0), WFEAT - 1);

    Geom g;
    g.wy_lo = y - (float)y1c;
    g.wy_hi = (float)y2c - y;
    g.wx_lo = x - (float)x1c;
    g.wx_hi = (float)x2c - x;
    g.wok = (g.wy_lo >= 0.0f) && (g.wy_lo <= 1.0f) && (g.wy_hi >= 0.0f) && (g.wy_hi <= 1.0f) &&
            (g.wx_lo >= 0.0f) && (g.wx_lo <= 1.0f) && (g.wx_hi >= 0.0f) && (g.wx_hi <= 1.0f);
    g.o11 = y1c * WFEAT + x1c;
    g.o12 = y1c * WFEAT + x2c;
    g.o21 = y2c * WFEAT + x1c;
    g.o22 = y2c * WFEAT + x2c;
    return g;
}

__device__ __forceinline__ float bilin(const float* __restrict__ base, const Geom& g) {
    float a = __ldg(base + g.o11);
    float b = __ldg(base + g.o12);
    float c = __ldg(base + g.o21);
    float d = __ldg(base + g.o22);
    return g.wy_hi * (g.wx_hi * a + g.wx_lo * b) +
           g.wy_lo * (g.wx_hi * c + g.wx_lo * d);
}

// ---------------------------------------------------------------------------
// Fused prep: blocks [0,1000) = colmax (per-pixel 16-block + total maxes),
// blocks [1000,1196) = seed (exact per-bin lower bound, plain store).
// Independent work co-scheduled in one wave: seed's L2 gathers hide under
// colmax's DRAM streaming.
// ---------------------------------------------------------------------------
__global__ void __launch_bounds__(256) k_prep(const float4* __restrict__ f4,
                                              const float* __restrict__ f,
                                              const float* __restrict__ rois) {
    __shared__ float s[64][NCB + 1];
    __shared__ float sred[NSEED];

    int bx = blockIdx.x;
    if (bx < COLMAX_BLOCKS) {
        // ---- colmax: 16 cb x 16 pixel-quads per block ----
        int qi = threadIdx.x & 15;          // quad within block
        int cb = threadIdx.x >> 4;          // channel block
        int pg = bx * 16 + qi;              // global pixel quad

        const float4* p = f4 + (size_t)(cb * CPB) * HW4 + pg;
        float4 m = make_float4(-CUDART_INF_F, -CUDART_INF_F, -CUDART_INF_F, -CUDART_INF_F);
#pragma unroll
        for (int j = 0; j < CPB; j++) {
            float4 v = __ldg(p + (size_t)j * HW4);
            m.x = fmaxf(m.x, v.x); m.y = fmaxf(m.y, v.y);
            m.z = fmaxf(m.z, v.z); m.w = fmaxf(m.w, v.w);
        }
        int lpx = qi * 4;
        s[lpx + 0][cb] = m.x;
        s[lpx + 1][cb] = m.y;
        s[lpx + 2][cb] = m.z;
        s[lpx + 3][cb] = m.w;
        __syncthreads();

        // coalesced g_Mb store: 64 px * 16 cb = 256 float4, one per thread
        int px  = threadIdx.x >> 2;
        int cb0 = (threadIdx.x & 3) * 4;
        float4 o = make_float4(s[px][cb0], s[px][cb0 + 1], s[px][cb0 + 2], s[px][cb0 + 3]);
        reinterpret_cast<float4*>(g_Mb + ((size_t)bx * 64) * NCB)[threadIdx.x] = o;

        // per-pixel total max (threads 0..63)
        if (threadIdx.x < 64) {
            float t = s[threadIdx.x][0];
#pragma unroll
            for (int k = 1; k < NCB; k++) t = fmaxf(t, s[threadIdx.x][k]);
            g_Tm[bx * 64 + threadIdx.x] = t;
        }
    } else {
        // ---- seed: one block per bin; warp w evals (roi w, sub 0) exactly ----
        int bin  = bx - COLMAX_BLOCKS;
        int w    = threadIdx.x >> 5;
        int lane = threadIdx.x & 31;
        int m = bin / MSZ;
        int n = bin - m * MSZ;

        Geom g = make_geom(rois, w, 0, m, n);
        float vmax = -CUDART_INF_F;
#pragma unroll
        for (int ci = 0; ci < CFEAT / 32; ci++)
            vmax = fmaxf(vmax, bilin(f + (size_t)(ci * 32 + lane) * HWFEAT, g));
#pragma unroll
        for (int o = 16; o; o >>= 1)
            vmax = fmaxf(vmax, __shfl_xor_sync(0xffffffffu, vmax, o));
        if (lane == 0) sred[w] = vmax;
        __syncthreads();
        if (threadIdx.x == 0) {
            float b = sred[0];
#pragma unroll
            for (int k = 1; k < NSEED; k++) b = fmaxf(b, sred[k]);
            g_best[bin] = b;    // plain store: one writer per bin, resets every replay
        }
    }
}

// ---------------------------------------------------------------------------
// Screened pass: block = bin, thread = candidate (512 per bin).
// Level 1 (per-thread): coarse upper bound from per-pixel total max g_Tm.
// Level 2 (per-warp, survivors only): 16-block bound from g_Mb (strictly
// tighter). Level 3: exact 256-channel eval, warp-cooperative.
// Pruning uses only exact lower bounds; tie-pruning is safe (if winner's
// ub <= best then best already equals the answer). Exact & deterministic.
// ---------------------------------------------------------------------------
__global__ void __launch_bounds__(512) k_points(const float* __restrict__ f,
                                                const float* __restrict__ rois) {
    int bin  = blockIdx.x;
    int cand = threadIdx.x;
    int lane = threadIdx.x & 31;
    int m = bin / MSZ;
    int n = bin - m * MSZ;

    Geom g = make_geom(rois, cand >> 2, cand & 3, m, n);
    float best = __ldg(&g_best[bin]);   // seeded exact lower bound

    // Level 1: coarse screen (one thread per candidate)
    float t11 = __ldg(&g_Tm[g.o11]);
    float t12 = __ldg(&g_Tm[g.o12]);
    float t21 = __ldg(&g_Tm[g.o21]);
    float t22 = __ldg(&g_Tm[g.o22]);
    float ub = g.wy_hi * (g.wx_hi * t11 + g.wx_lo * t12) +
               g.wy_lo * (g.wx_hi * t21 + g.wx_lo * t22);
    bool need = (!g.wok) || (ub > best);

    unsigned mask = __ballot_sync(0xffffffffu, need);
    float gmax = -CUDART_INF_F;
    bool  wrote = false;

    while (mask) {
        int src = __ffs(mask) - 1;
        mask &= mask - 1;
        int sc = (threadIdx.x & ~31) + src;            // survivor candidate (warp-uniform)
        Geom g2 = make_geom(rois, sc >> 2, sc & 3, m, n);

        // refresh best (other warps' atomics tighten pruning; stale is safe)
        best = fmaxf(best, __ldg(&g_best[bin]));

        // Level 2: fine 16-block screen
        bool fneed = !g2.wok;
        if (lane < NCB) {
            float m11 = __ldg(&g_Mb[(size_t)g2.o11 * NCB + lane]);
            float m12 = __ldg(&g_Mb[(size_t)g2.o12 * NCB + lane]);
            float m21 = __ldg(&g_Mb[(size_t)g2.o21 * NCB + lane]);
            float m22 = __ldg(&g_Mb[(size_t)g2.o22 * NCB + lane]);
            float ubf = g2.wy_hi * (g2.wx_hi * m11 + g2.wx_lo * m12) +
                        g2.wy_lo * (g2.wx_hi * m21 + g2.wx_lo * m22);
            fneed = fneed || (ubf > best);
        }
        if (__any_sync(0xffffffffu, fneed)) {
            // Level 3: exact eval over all 256 channels
            float v = -CUDART_INF_F;
#pragma unroll
            for (int ci = 0; ci < CFEAT / 32; ci++)
                v = fmaxf(v, bilin(f + (size_t)(ci * 32 + lane) * HWFEAT, g2));
#pragma unroll
            for (int o = 16; o; o >>= 1)
                v = fmaxf(v, __shfl_xor_sync(0xffffffffu, v, o));
            best = fmaxf(best, v);
            gmax = fmaxf(gmax, v);
            wrote = true;
        }
    }
    if (wrote && lane == 0) atomicMaxFloat(&g_best[bin], gmax);
}

// ---------------------------------------------------------------------------
// Broadcast g_best[196] to out[R, C, 14, 14]: 784 blocks, 8 float4/thread.
// ---------------------------------------------------------------------------
__global__ void __launch_bounds__(256) k_bcast(float4* __restrict__ out) {
    __shared__ float4 sb[NBIN / 4];
    if (threadIdx.x < NBIN / 4)
        sb[threadIdx.x] = reinterpret_cast<const float4*>(g_best)[threadIdx.x];
    __syncthreads();
    int base = blockIdx.x * 2048 + threadIdx.x;
#pragma unroll
    for (int k = 0; k < 8; k++) {
        int i = base + k * 256;
        out[i] = sb[i % (NBIN / 4)];
    }
}

// ---------------------------------------------------------------------------
extern "C" void kernel_launch(void* const* d_in, const int* in_sizes, int n_in,
                              void* d_out, int out_size) {
    const float* feature = (const float*)d_in[0];   // [1,256,200,320] f32
    const float* rois    = (const float*)d_in[1];   // [128,4] f32
    float* out           = (float*)d_out;           // [128,256,14,14] f32

    // Fused colmax + seed (independent, co-scheduled)
    k_prep<<<PREP_BLOCKS, 256>>>((const float4*)feature, feature, rois);

    // Three-level screened pass over all (bin, candidate) pairs
    k_points<<<NBIN, 512>>>(feature, rois);

    // Broadcast result: out_size/4 = 1605632 = 784 * 2048
    k_bcast<<<784, 256>>>((float4*)out);
}

// round 9
// speedup vs baseline: 2.8124x; 2.8124x over previous
#include <cuda_runtime.h>
#include <math_constants.h>

#define HFEAT 200
#define WFEAT 320
#define HWFEAT (HFEAT * WFEAT)      // 64000 pixels
#define HW4 (HWFEAT / 4)            // 16000 pixel-quads
#define CFEAT 256
#define NROI 128
#define MSZ 14
#define NBIN (MSZ * MSZ)            // 196
#define NCB 16                      // fine channel blocks (16 channels each)
#define CPB 16
#define NCAND (NROI * 4)            // 512 candidates per bin
#define NSEED 8                     // seed rois per bin
#define COLMAX_BLOCKS (HW4 / 16)    // 1000
#define PREP_BLOCKS (COLMAX_BLOCKS + NBIN)

// Scratch (static device arrays — no allocation)
__device__ __align__(16) float g_Mb[HWFEAT * NCB];   // per-pixel 16-ch block maxes (4 MB)
__device__ __align__(16) float g_Tm[HWFEAT];         // per-pixel total max (256 KB)
__device__ __align__(16) float g_best[NBIN];         // per-bin exact lower bound -> final max

// ---------------------------------------------------------------------------
__device__ __forceinline__ void atomicMaxFloat(float* addr, float val) {
    if (val >= 0.0f) {
        atomicMax((int*)addr, __float_as_int(val));
    } else {
        atomicMin((unsigned int*)addr, __float_as_uint(val));
    }
}

// ---------------------------------------------------------------------------
// Geometry: replicate the reference bilinear setup exactly
// (corner indices clamped FIRST, weights computed from clamped corners).
// ---------------------------------------------------------------------------
struct Geom {
    int o11, o12, o21, o22;
    float wy_lo, wy_hi, wx_lo, wx_hi;
    bool wok;   // weights are a convex combination (clamp did not trigger)
};

__device__ __forceinline__ Geom make_geom(const float* __restrict__ rois,
                                          int r, int s, int m, int n) {
    float r0 = __ldg(&rois[r * 4 + 0]);
    float r1 = __ldg(&rois[r * 4 + 1]);
    float r2 = __ldg(&rois[r * 4 + 2]);
    float r3 = __ldg(&rois[r * 4 + 3]);
    float sh = (r2 - r0) / 14.0f;
    float sw = (r3 - r1) / 14.0f;
    float fy = (s >> 1) ? (2.0f / 3.0f) : (1.0f / 3.0f);
    float fx = (s & 1)  ? (2.0f / 3.0f) : (1.0f / 3.0f);
    float y = (r0 + sh * (float)m) + sh * fy;
    float x = (r1 + sw * (float)n) + sw * fx;

    int yf = (int)floorf(y);
    int xf = (int)floorf(x);
    int y1c = min(max(yf, 0), HFEAT - 1);
    int y2c = min(max(yf + 1, 0), HFEAT - 1);
    int x1c = min(max(xf, 0), WFEAT - 1);
    int x2c = min(max(xf + 1, 0), WFEAT - 1);

    Geom g;
    g.wy_lo = y - (float)y1c;
    g.wy_hi = (float)y2c - y;
    g.wx_lo = x - (float)x1c;
    g.wx_hi = (float)x2c - x;
    g.wok = (g.wy_lo >= 0.0f) && (g.wy_lo <= 1.0f) && (g.wy_hi >= 0.0f) && (g.wy_hi <= 1.0f) &&
            (g.wx_lo >= 0.0f) && (g.wx_lo <= 1.0f) && (g.wx_hi >= 0.0f) && (g.wx_hi <= 1.0f);
    g.o11 = y1c * WFEAT + x1c;
    g.o12 = y1c * WFEAT + x2c;
    g.o21 = y2c * WFEAT + x1c;
    g.o22 = y2c * WFEAT + x2c;
    return g;
}

__device__ __forceinline__ float bilin(const float* __restrict__ base, const Geom& g) {
    float a = __ldg(base + g.o11);
    float b = __ldg(base + g.o12);
    float c = __ldg(base + g.o21);
    float d = __ldg(base + g.o22);
    return g.wy_hi * (g.wx_hi * a + g.wx_lo * b) +
           g.wy_lo * (g.wx_hi * c + g.wx_lo * d);
}

// ---------------------------------------------------------------------------
// Fused prep. Blocks [0,196) = seed (launched FIRST so their scattered
// gathers overlap colmax's streaming in wave 1); blocks [196,1196) = colmax.
// Seed: one block per bin, warp w exactly evaluates (roi w, sub 0) over all
// 256 channels; plain store of the block max into g_best (single writer, so
// every graph replay resets to the same value).
// Colmax: per-pixel 16-channel-block maxes + per-pixel total max.
// ---------------------------------------------------------------------------
__global__ void __launch_bounds__(256) k_prep(const float4* __restrict__ f4,
                                              const float* __restrict__ f,
                                              const float* __restrict__ rois) {
    __shared__ float s[64][NCB + 1];
    __shared__ float sred[NSEED];

    int bx = blockIdx.x;
    if (bx < NBIN) {
        // ---- seed ----
        int bin  = bx;
        int w    = threadIdx.x >> 5;
        int lane = threadIdx.x & 31;
        int m = bin / MSZ;
        int n = bin - m * MSZ;

        Geom g = make_geom(rois, w, 0, m, n);
        float vmax = -CUDART_INF_F;
#pragma unroll
        for (int ci = 0; ci < CFEAT / 32; ci++)
            vmax = fmaxf(vmax, bilin(f + (size_t)(ci * 32 + lane) * HWFEAT, g));
#pragma unroll
        for (int o = 16; o; o >>= 1)
            vmax = fmaxf(vmax, __shfl_xor_sync(0xffffffffu, vmax, o));
        if (lane == 0) sred[w] = vmax;
        __syncthreads();
        if (threadIdx.x == 0) {
            float b = sred[0];
#pragma unroll
            for (int k = 1; k < NSEED; k++) b = fmaxf(b, sred[k]);
            g_best[bin] = b;
        }
    } else {
        // ---- colmax: 16 cb x 16 pixel-quads per block ----
        int cbx = bx - NBIN;
        int qi = threadIdx.x & 15;
        int cb = threadIdx.x >> 4;
        int pg = cbx * 16 + qi;

        const float4* p = f4 + (size_t)(cb * CPB) * HW4 + pg;
        float4 m = make_float4(-CUDART_INF_F, -CUDART_INF_F, -CUDART_INF_F, -CUDART_INF_F);
#pragma unroll
        for (int j = 0; j < CPB; j++) {
            float4 v = __ldg(p + (size_t)j * HW4);
            m.x = fmaxf(m.x, v.x); m.y = fmaxf(m.y, v.y);
            m.z = fmaxf(m.z, v.z); m.w = fmaxf(m.w, v.w);
        }
        int lpx = qi * 4;
        s[lpx + 0][cb] = m.x;
        s[lpx + 1][cb] = m.y;
        s[lpx + 2][cb] = m.z;
        s[lpx + 3][cb] = m.w;
        __syncthreads();

        // coalesced g_Mb store: 64 px * 16 cb = 256 float4, one per thread
        int px  = threadIdx.x >> 2;
        int cb0 = (threadIdx.x & 3) * 4;
        float4 o = make_float4(s[px][cb0], s[px][cb0 + 1], s[px][cb0 + 2], s[px][cb0 + 3]);
        reinterpret_cast<float4*>(g_Mb + ((size_t)cbx * 64) * NCB)[threadIdx.x] = o;

        // per-pixel total max (threads 0..63)
        if (threadIdx.x < 64) {
            float t = s[threadIdx.x][0];
#pragma unroll
            for (int k = 1; k < NCB; k++) t = fmaxf(t, s[threadIdx.x][k]);
            g_Tm[cbx * 64 + threadIdx.x] = t;
        }
    }
}

// ---------------------------------------------------------------------------
// Screened pass. Grid (196, 2) x 256: thread = one candidate.
// Level 1 (per-thread): coarse bound from per-pixel total max g_Tm.
// Level 2 (per survivor, 16 lanes): per-channel-block bounds from g_Mb.
// Level 3: evaluate ONLY the blocks whose bound beats best (2 blocks at a
// time across the warp, 16 channels per half). This per-block granularity is
// the load-bearing part (R8's whole-warp eval regressed 4x).
// g_best holds only exact achieved values => pruning exact & deterministic.
// ---------------------------------------------------------------------------
__global__ void __launch_bounds__(256) k_points(const float* __restrict__ f,
                                                const float* __restrict__ rois) {
    int bin  = blockIdx.x;
    int cand = blockIdx.y * 256 + threadIdx.x;   // 0..511
    int lane = threadIdx.x & 31;
    int m = bin / MSZ;
    int n = bin - m * MSZ;

    Geom g = make_geom(rois, cand >> 2, cand & 3, m, n);
    float best = __ldg(&g_best[bin]);            // seeded exact lower bound

    // Level 1: coarse screen, one thread per candidate
    float ub = g.wy_hi * (g.wx_hi * __ldg(&g_Tm[g.o11]) + g.wx_lo * __ldg(&g_Tm[g.o12])) +
               g.wy_lo * (g.wx_hi * __ldg(&g_Tm[g.o21]) + g.wx_lo * __ldg(&g_Tm[g.o22]));
    bool need = (!g.wok) || (ub > best);

    unsigned smask = __ballot_sync(0xffffffffu, need);
    if (!smask) return;

    float gmax = -CUDART_INF_F;
    bool  wrote = false;

    while (smask) {
        int src = __ffs(smask) - 1;
        smask &= smask - 1;

        // broadcast survivor's geometry
        Geom g2;
        g2.o11   = __shfl_sync(0xffffffffu, g.o11, src);
        g2.o12   = __shfl_sync(0xffffffffu, g.o12, src);
        g2.o21   = __shfl_sync(0xffffffffu, g.o21, src);
        g2.o22   = __shfl_sync(0xffffffffu, g.o22, src);
        g2.wy_lo = __shfl_sync(0xffffffffu, g.wy_lo, src);
        g2.wy_hi = __shfl_sync(0xffffffffu, g.wy_hi, src);
        g2.wx_lo = __shfl_sync(0xffffffffu, g.wx_lo, src);
        g2.wx_hi = __shfl_sync(0xffffffffu, g.wx_hi, src);
        int wok2 = __shfl_sync(0xffffffffu, (int)g.wok, src);

        // refresh best (other warps' atomics tighten pruning; stale is safe)
        best = fmaxf(best, __ldcg(&g_best[bin]));

        // Level 2: per-block fine bounds (lanes 0..15)
        bool fneed = false;
        if (lane < NCB) {
            float m11 = __ldg(&g_Mb[(size_t)g2.o11 * NCB + lane]);
            float m12 = __ldg(&g_Mb[(size_t)g2.o12 * NCB + lane]);
            float m21 = __ldg(&g_Mb[(size_t)g2.o21 * NCB + lane]);
            float m22 = __ldg(&g_Mb[(size_t)g2.o22 * NCB + lane]);
            float ubf = g2.wy_hi * (g2.wx_hi * m11 + g2.wx_lo * m12) +
                        g2.wy_lo * (g2.wx_hi * m21 + g2.wx_lo * m22);
            fneed = ubf > best;
        }
        unsigned bmask = __ballot_sync(0xffffffffu, fneed) & 0xFFFFu;
        if (!wok2) bmask = 0xFFFFu;
        if (!bmask) continue;

        // Level 3: evaluate only surviving blocks, two at a time
        float v = -CUDART_INF_F;
        while (bmask) {
            int cb0 = __ffs(bmask) - 1;
            bmask &= bmask - 1;
            int cb1 = cb0;
            if (bmask) { cb1 = __ffs(bmask) - 1; bmask &= bmask - 1; }
            int cb = (lane < 16) ? cb0 : cb1;
            const float* fc = f + (size_t)(cb * CPB + (lane & 15)) * HWFEAT;
            v = fmaxf(v, bilin(fc, g2));
        }
#pragma unroll
        for (int o = 16; o; o >>= 1)
            v = fmaxf(v, __shfl_xor_sync(0xffffffffu, v, o));
        best = fmaxf(best, v);
        gmax = fmaxf(gmax, v);
        wrote = true;
    }
    if (wrote && lane == 0) atomicMaxFloat(&g_best[bin], gmax);
}

// ---------------------------------------------------------------------------
// Broadcast g_best[196] to out[R, C, 14, 14]: 784 blocks, 8 float4/thread.
// ---------------------------------------------------------------------------
__global__ void __launch_bounds__(256) k_bcast(float4* __restrict__ out) {
    __shared__ float4 sb[NBIN / 4];
    if (threadIdx.x < NBIN / 4)
        sb[threadIdx.x] = reinterpret_cast<const float4*>(g_best)[threadIdx.x];
    __syncthreads();
    int base = blockIdx.x * 2048 + threadIdx.x;
#pragma unroll
    for (int k = 0; k < 8; k++) {
        int i = base + k * 256;
        out[i] = sb[i % (NBIN / 4)];
    }
}

// ---------------------------------------------------------------------------
extern "C" void kernel_launch(void* const* d_in, const int* in_sizes, int n_in,
                              void* d_out, int out_size) {
    const float* feature = (const float*)d_in[0];   // [1,256,200,320] f32
    const float* rois    = (const float*)d_in[1];   // [128,4] f32
    float* out           = (float*)d_out;           // [128,256,14,14] f32

    // Fused seed + colmax (seed first: overlaps colmax streaming in wave 1)
    k_prep<<<PREP_BLOCKS, 256>>>((const float4*)feature, feature, rois);

    // Three-level screened pass (coarse per-thread, fine per-block, eval per-block)
    dim3 g2(NBIN, 2);
    k_points<<<g2, 256>>>(feature, rois);

    // Broadcast result: out_size/4 = 1605632 = 784 * 2048
    k_bcast<<<784, 256>>>((float4*)out);
}